// round 9
// baseline (speedup 1.0000x reference)
#include <cuda_runtime.h>
#include <cuda_bf16.h>
#include <cuda_fp8.h>
#include <cstdint>
#include <math.h>

// ---------------- problem constants ----------------
#define BDIM   4096          // batch rows
#define KDIM   4096          // F + S
#define NGATE  6144          // 3*S
#define SDIM   2048
#define HSIZE  8388608L      // B*S

// ---------------- tile config ----------------
// Main product A0*B0 in bf16 (m16n8k16); corrections A1*B0 + A0*B1 in e4m3
// (m16n8k32) with scales baked into operands (A1q=16*a1, B0c=b0/16, etc.) so
// all three products accumulate into ONE fp32 accumulator.
#define BM 128
#define BNS 32               // state-columns per CTA; B tile = 3 gates x 32 = 96 rows
#define BNROWS 96
#define BK 32                // k per chunk: 2 bf16 k16 slices, 1 fp8 k32 slice
#define KT (KDIM / BK)       // 128 chunks
#define STAGES 2
#define NTHREADS 128

// smem: row stride 80B, conflict-free for ldmatrix (offsets mod 128 distinct)
#define ROWB 80
#define A0_T (BM * ROWB)                  // 10240  bf16 A0 (64B data + pad)
#define AF8_T (BM * ROWB)                 // 10240  fp8 A0c|A1q (32B+32B data + pad)
#define B0_T (BNROWS * ROWB)              // 7680   bf16 B0
#define BF8_T (BNROWS * ROWB)             // 7680   fp8 B0c|B1q
#define STAGE_BYTES (A0_T + AF8_T + B0_T + BF8_T)   // 35840
#define SMEM_TOTAL (STAGES * STAGE_BYTES)           // 71680 (x3 CTAs = 215KB/SM)

// ---------------- scratch (no cudaMalloc allowed) ----------------
__device__ __nv_bfloat16 g_A0[(long)BDIM * KDIM];    // 32MB  bf16(X)
__device__ uint8_t g_A0c[(long)BDIM * KDIM];         // 16MB  e4m3(bf16(X)/16)
__device__ uint8_t g_A1q[(long)BDIM * KDIM];         // 16MB  e4m3(16*(X-bf16(X)))
__device__ __nv_bfloat16 g_B0[(long)NGATE * KDIM];   // 50MB  bf16(W^T)
__device__ uint8_t g_B0c[(long)NGATE * KDIM];        // 25MB  e4m3(bf16(W^T)/16)
__device__ uint8_t g_B1q[(long)NGATE * KDIM];        // 25MB  e4m3(16*(W^T-bf16))

// ---------------- helpers ----------------
__device__ __forceinline__ uint32_t smem_u32(const void* p) {
    uint32_t a;
    asm("{ .reg .u64 t; cvta.to.shared.u64 t, %1; cvt.u32.u64 %0, t; }" : "=r"(a) : "l"(p));
    return a;
}
__device__ __forceinline__ void cp16(uint32_t dst, const void* src) {
    asm volatile("cp.async.cg.shared.global [%0], [%1], 16;" :: "r"(dst), "l"(src) : "memory");
}
__device__ __forceinline__ void cp_commit() {
    asm volatile("cp.async.commit_group;" ::: "memory");
}
template <int N>
__device__ __forceinline__ void cp_wait() {
    asm volatile("cp.async.wait_group %0;" :: "n"(N) : "memory");
}
__device__ __forceinline__ void ldsm4(uint32_t& r0, uint32_t& r1, uint32_t& r2, uint32_t& r3,
                                      uint32_t addr) {
    asm volatile("ldmatrix.sync.aligned.m8n8.x4.shared.b16 {%0,%1,%2,%3}, [%4];"
                 : "=r"(r0), "=r"(r1), "=r"(r2), "=r"(r3) : "r"(addr));
}
__device__ __forceinline__ void mma_bf16(float* c, const uint32_t* a, const uint32_t* b) {
    asm volatile(
        "mma.sync.aligned.m16n8k16.row.col.f32.bf16.bf16.f32 "
        "{%0,%1,%2,%3}, {%4,%5,%6,%7}, {%8,%9}, {%0,%1,%2,%3};"
        : "+f"(c[0]), "+f"(c[1]), "+f"(c[2]), "+f"(c[3])
        : "r"(a[0]), "r"(a[1]), "r"(a[2]), "r"(a[3]), "r"(b[0]), "r"(b[1]));
}
__device__ __forceinline__ void mma_fp8(float* c, const uint32_t* a, const uint32_t* b) {
    asm volatile(
        "mma.sync.aligned.m16n8k32.row.col.f32.e4m3.e4m3.f32 "
        "{%0,%1,%2,%3}, {%4,%5,%6,%7}, {%8,%9}, {%0,%1,%2,%3};"
        : "+f"(c[0]), "+f"(c[1]), "+f"(c[2]), "+f"(c[3])
        : "r"(a[0]), "r"(a[1]), "r"(a[2]), "r"(a[3]), "r"(b[0]), "r"(b[1]));
}
__device__ __forceinline__ uint8_t to_e4m3(float x) {
    __nv_fp8_e4m3 q(x);
    return *reinterpret_cast<uint8_t*>(&q);
}

// ---------------- prologue: pack & split X = [old_h | input] ----------------
__global__ void pack_split_x(const float* __restrict__ old_h, const float* __restrict__ input,
                             __nv_bfloat16* __restrict__ A0, uint8_t* __restrict__ A0c,
                             uint8_t* __restrict__ A1q) {
    long i = (long)blockIdx.x * blockDim.x + threadIdx.x;   // float4 units, 4096*1024
    int m = (int)(i >> 10);
    int kq = (int)(i & 1023);
    float4 v = (kq < 512) ? reinterpret_cast<const float4*>(old_h)[(long)m * 512 + kq]
                          : reinterpret_cast<const float4*>(input)[(long)m * 512 + (kq - 512)];
    const float* xs = &v.x;
    __nv_bfloat16 h0[4];
    uint8_t c8[4], r8[4];
#pragma unroll
    for (int j = 0; j < 4; j++) {
        float x = xs[j];
        h0[j] = __float2bfloat16_rn(x);
        float f0 = __bfloat162float(h0[j]);
        c8[j] = to_e4m3(f0 * 0.0625f);
        r8[j] = to_e4m3((x - f0) * 16.0f);
    }
    *reinterpret_cast<uint2*>(&A0[4 * i]) = *reinterpret_cast<uint2*>(h0);
    *reinterpret_cast<uint32_t*>(&A0c[4 * i]) = *reinterpret_cast<uint32_t*>(c8);
    *reinterpret_cast<uint32_t*>(&A1q[4 * i]) = *reinterpret_cast<uint32_t*>(r8);
}

// ---------------- prologue: transpose & split W -> Wt[n][k] ----------------
__global__ void split_w_kernel(const float* __restrict__ W, __nv_bfloat16* __restrict__ B0,
                               uint8_t* __restrict__ B0c, uint8_t* __restrict__ B1q) {
    __shared__ float tile[32][33];
    int n0 = blockIdx.x * 32, k0 = blockIdx.y * 32;
    int tx = threadIdx.x, ty = threadIdx.y;
#pragma unroll
    for (int i = 0; i < 32; i += 8)
        tile[ty + i][tx] = W[(long)(k0 + ty + i) * NGATE + n0 + tx];
    __syncthreads();
#pragma unroll
    for (int i = 0; i < 32; i += 8) {
        long n = n0 + ty + i, k = k0 + tx;
        float w = tile[tx][ty + i];
        __nv_bfloat16 h0 = __float2bfloat16_rn(w);
        float f0 = __bfloat162float(h0);
        B0[n * KDIM + k] = h0;
        B0c[n * KDIM + k] = to_e4m3(f0 * 0.0625f);
        B1q[n * KDIM + k] = to_e4m3((w - f0) * 16.0f);
    }
}

// ---------------- fused GEMM + LLTM epilogue ----------------
// CTA: 128 rows x 32 state-cols x 3 gates. 4 warps 4(m)x1(n), warp tile 32x96.
__global__ void __launch_bounds__(NTHREADS, 3) lltm_fused_kernel(
    const float* __restrict__ bias, const float* __restrict__ old_c,
    float* __restrict__ out) {
    extern __shared__ char smem[];
    const uint32_t sbase = smem_u32(smem);

    const int tid = threadIdx.x;
    const int warp = tid >> 5, lane = tid & 31;
    const int g = lane >> 2, t4 = lane & 3;
    const long m0 = (long)blockIdx.x * BM;
    const int n0s = blockIdx.y * BNS;        // state-column base (0..2047)

    float acc[2][12][4];
#pragma unroll
    for (int i = 0; i < 2; i++)
#pragma unroll
        for (int j = 0; j < 12; j++)
#pragma unroll
            for (int r = 0; r < 4; r++) acc[i][j][r] = 0.0f;

    // per-lane ldmatrix offsets (within a tile) — same formula for bf16 & fp8 tiles
    const uint32_t a_off = (uint32_t)(warp * 32 + (lane & 15)) * ROWB + ((lane >> 4) << 4);
    const uint32_t b_off =
        (uint32_t)((lane & 7) + ((lane >> 4) << 3)) * ROWB + (((lane >> 3) & 1) << 4);

    auto issue_stage = [&](int t) {
        int slot = t & (STAGES - 1);
        long kk = (long)t * BK;
        uint32_t sA0 = sbase + slot * STAGE_BYTES;
        uint32_t sAf8 = sA0 + A0_T;
        uint32_t sB0 = sAf8 + AF8_T;
        uint32_t sBf8 = sB0 + B0_T;
#pragma unroll
        for (int i = 0; i < 4; i++) {
            int q = tid + i * NTHREADS;
            int row = q >> 2, cw = q & 3;
            // bf16 A0: 64B/row
            cp16(sA0 + row * ROWB + cw * 16, g_A0 + (m0 + row) * KDIM + kk + cw * 8);
            // fp8: bytes 0-31 = A0c, 32-63 = A1q
            const uint8_t* src8 = (cw < 2) ? (g_A0c + (m0 + row) * KDIM + kk + cw * 16)
                                           : (g_A1q + (m0 + row) * KDIM + kk + (cw - 2) * 16);
            cp16(sAf8 + row * ROWB + cw * 16, src8);
        }
#pragma unroll
        for (int i = 0; i < 3; i++) {
            int q = tid + i * NTHREADS;
            int row = q >> 2, cw = q & 3;        // row 0..95
            long grow = (long)(row >> 5) * SDIM + n0s + (row & 31);
            cp16(sB0 + row * ROWB + cw * 16, g_B0 + grow * KDIM + kk + cw * 8);
            const uint8_t* src8 = (cw < 2) ? (g_B0c + grow * KDIM + kk + cw * 16)
                                           : (g_B1q + grow * KDIM + kk + (cw - 2) * 16);
            cp16(sBf8 + row * ROWB + cw * 16, src8);
        }
    };

    issue_stage(0);
    cp_commit();

    for (int t = 0; t < KT; t++) {
        cp_wait<0>();
        __syncthreads();

        if (t + 1 < KT) issue_stage(t + 1);
        cp_commit();

        uint32_t sA0 = sbase + (t & (STAGES - 1)) * STAGE_BYTES;
        uint32_t sAf8 = sA0 + A0_T;
        uint32_t sB0 = sAf8 + AF8_T;
        uint32_t sBf8 = sB0 + B0_T;

        // ---- main bf16 product: 2 k16 slices ----
#pragma unroll
        for (int s = 0; s < 2; s++) {
            const uint32_t ks = (uint32_t)s * 32;
            uint32_t a[2][4], b[12][2];
#pragma unroll
            for (int i = 0; i < 2; i++)
                ldsm4(a[i][0], a[i][1], a[i][2], a[i][3],
                      sA0 + a_off + (uint32_t)i * (16 * ROWB) + ks);
#pragma unroll
            for (int jj = 0; jj < 6; jj++)
                ldsm4(b[2 * jj][0], b[2 * jj][1], b[2 * jj + 1][0], b[2 * jj + 1][1],
                      sB0 + b_off + (uint32_t)jj * (16 * ROWB) + ks);
#pragma unroll
            for (int i = 0; i < 2; i++)
#pragma unroll
                for (int j = 0; j < 12; j++) mma_bf16(acc[i][j], a[i], b[j]);
        }

        // ---- fp8 corrections: one k32 slice ----
        {
            uint32_t a1[2][4], a0c[2][4], b[12][2];
#pragma unroll
            for (int i = 0; i < 2; i++) {
                ldsm4(a1[i][0], a1[i][1], a1[i][2], a1[i][3],
                      sAf8 + a_off + (uint32_t)i * (16 * ROWB) + 32);   // A1q bytes 32-63
                ldsm4(a0c[i][0], a0c[i][1], a0c[i][2], a0c[i][3],
                      sAf8 + a_off + (uint32_t)i * (16 * ROWB));        // A0c bytes 0-31
            }
            // A1q x B0c
#pragma unroll
            for (int jj = 0; jj < 6; jj++)
                ldsm4(b[2 * jj][0], b[2 * jj][1], b[2 * jj + 1][0], b[2 * jj + 1][1],
                      sBf8 + b_off + (uint32_t)jj * (16 * ROWB));
#pragma unroll
            for (int i = 0; i < 2; i++)
#pragma unroll
                for (int j = 0; j < 12; j++) mma_fp8(acc[i][j], a1[i], b[j]);
            // A0c x B1q
#pragma unroll
            for (int jj = 0; jj < 6; jj++)
                ldsm4(b[2 * jj][0], b[2 * jj][1], b[2 * jj + 1][0], b[2 * jj + 1][1],
                      sBf8 + b_off + (uint32_t)jj * (16 * ROWB) + 32);
#pragma unroll
            for (int i = 0; i < 2; i++)
#pragma unroll
                for (int j = 0; j < 12; j++) mma_fp8(acc[i][j], a0c[i], b[j]);
        }
    }

    // ---- fused LLTM epilogue ----
#pragma unroll
    for (int i = 0; i < 2; i++) {
        long row0 = m0 + warp * 32 + i * 16 + g;
#pragma unroll
        for (int sj = 0; sj < 4; sj++) {
            int col = n0s + sj * 8 + 2 * t4;
            float2 bi = *reinterpret_cast<const float2*>(&bias[col]);
            float2 bo = *reinterpret_cast<const float2*>(&bias[SDIM + col]);
            float2 bc = *reinterpret_cast<const float2*>(&bias[2 * SDIM + col]);
            const float* ai = acc[i][sj];
            const float* ao = acc[i][sj + 4];
            const float* ac = acc[i][sj + 8];
#pragma unroll
            for (int h = 0; h < 2; h++) {        // h=0: row0, h=1: row0+8
                long row = row0 + 8 * h;
                float2 oc = *reinterpret_cast<const float2*>(&old_c[row * SDIM + col]);
                float2 nh, ncell;
#define LANE(f, idx)                                                    \
                {                                                       \
                    float vi = ai[2 * h + idx] + bi.f;                  \
                    float vo = ao[2 * h + idx] + bo.f;                  \
                    float vc = ac[2 * h + idx] + bc.f;                  \
                    float ig = 1.0f / (1.0f + expf(-vi));               \
                    float og = 1.0f / (1.0f + expf(-vo));               \
                    float cc = (vc > 0.0f) ? vc : expm1f(vc);           \
                    float cell = oc.f + cc * ig;                        \
                    ncell.f = cell;                                     \
                    nh.f = tanhf(cell) * og;                            \
                }
                LANE(x, 0) LANE(y, 1)
#undef LANE
                *reinterpret_cast<float2*>(&out[row * SDIM + col]) = nh;
                *reinterpret_cast<float2*>(&out[HSIZE + row * SDIM + col]) = ncell;
            }
        }
    }
}

// ---------------- host ----------------
extern "C" void kernel_launch(void* const* d_in, const int* in_sizes, int n_in,
                              void* d_out, int out_size) {
    const float* W     = (const float*)d_in[0];   // (4096, 6144)
    const float* bias  = (const float*)d_in[1];   // (6144,)
    const float* input = (const float*)d_in[2];   // (4096, 2048)
    const float* old_h = (const float*)d_in[3];   // (4096, 2048)
    const float* old_c = (const float*)d_in[4];   // (4096, 2048)
    float* out = (float*)d_out;                   // [new_h | new_cell]

    void *pA0, *pA0c, *pA1q, *pB0, *pB0c, *pB1q;
    cudaGetSymbolAddress(&pA0, g_A0);
    cudaGetSymbolAddress(&pA0c, g_A0c);
    cudaGetSymbolAddress(&pA1q, g_A1q);
    cudaGetSymbolAddress(&pB0, g_B0);
    cudaGetSymbolAddress(&pB0c, g_B0c);
    cudaGetSymbolAddress(&pB1q, g_B1q);

    pack_split_x<<<16384, 256>>>(old_h, input, (__nv_bfloat16*)pA0, (uint8_t*)pA0c,
                                 (uint8_t*)pA1q);
    split_w_kernel<<<dim3(NGATE / 32, KDIM / 32), dim3(32, 8)>>>(
        W, (__nv_bfloat16*)pB0, (uint8_t*)pB0c, (uint8_t*)pB1q);

    cudaFuncSetAttribute(lltm_fused_kernel, cudaFuncAttributeMaxDynamicSharedMemorySize,
                         SMEM_TOTAL);
    lltm_fused_kernel<<<dim3(BDIM / BM, SDIM / BNS), NTHREADS, SMEM_TOTAL>>>(bias, old_c, out);
}

// round 10
// speedup vs baseline: 1.2598x; 1.2598x over previous
#include <cuda_runtime.h>
#include <cuda_fp16.h>
#include <cstdint>
#include <math.h>

// ---------------- problem constants ----------------
#define BDIM   4096          // batch rows
#define KDIM   4096          // F + S
#define NGATE  6144          // 3*S
#define SDIM   2048
#define HSIZE  8388608L      // B*S

// ---------------- tile config: fp16-split 3-product scheme ----------------
// X = A0 + A1 (fp16 + fp16 residual), W^T = B0 + B1.
// main:  A0*B0  -> fp32 accumulators (m16n8k16.f32.f16.f16.f32)
// corr:  A1*B0 + A0*B1 -> fp16 accumulators (m16n8k16.f16.f16.f16.f16)
// gate = acc32 + f16tof32(acc16). Dropped term A1*B1 ~ 2^-22.
#define BM 128
#define BNS 32               // state-cols per CTA; B tile = 3 gates x 32 = 96 rows
#define BNROWS 96
#define BK 32                // 2 k16 slices per chunk
#define KT (KDIM / BK)       // 128 chunks
#define STAGES 3
#define NTHREADS 128

// smem: row stride 80B (64B data + 16 pad), conflict-free ldmatrix/cp.async
#define ROWB 80
#define A_T (BM * ROWB)                   // 10240 per A tile
#define B_T (BNROWS * ROWB)               // 7680 per B tile
#define STAGE_BYTES (2 * A_T + 2 * B_T)   // 35840
#define SMEM_TOTAL (STAGES * STAGE_BYTES) // 107520 (x2 CTAs = 215KB/SM)

// ---------------- scratch (no cudaMalloc allowed) ----------------
__device__ __half g_A0[(long)BDIM * KDIM];    // 32MB  fp16(X)
__device__ __half g_A1[(long)BDIM * KDIM];    // 32MB  fp16(X - A0)
__device__ __half g_B0[(long)NGATE * KDIM];   // 50MB  fp16(W^T)
__device__ __half g_B1[(long)NGATE * KDIM];   // 50MB  fp16(W^T - B0)

// ---------------- helpers ----------------
__device__ __forceinline__ uint32_t smem_u32(const void* p) {
    uint32_t a;
    asm("{ .reg .u64 t; cvta.to.shared.u64 t, %1; cvt.u32.u64 %0, t; }" : "=r"(a) : "l"(p));
    return a;
}
__device__ __forceinline__ void cp16(uint32_t dst, const void* src) {
    asm volatile("cp.async.cg.shared.global [%0], [%1], 16;" :: "r"(dst), "l"(src) : "memory");
}
__device__ __forceinline__ void cp_commit() {
    asm volatile("cp.async.commit_group;" ::: "memory");
}
template <int N>
__device__ __forceinline__ void cp_wait() {
    asm volatile("cp.async.wait_group %0;" :: "n"(N) : "memory");
}
__device__ __forceinline__ void ldsm4(uint32_t& r0, uint32_t& r1, uint32_t& r2, uint32_t& r3,
                                      uint32_t addr) {
    asm volatile("ldmatrix.sync.aligned.m8n8.x4.shared.b16 {%0,%1,%2,%3}, [%4];"
                 : "=r"(r0), "=r"(r1), "=r"(r2), "=r"(r3) : "r"(addr));
}
// main product: fp16 operands, fp32 accumulate
__device__ __forceinline__ void mma_f32acc(float* c, const uint32_t* a, const uint32_t* b) {
    asm volatile(
        "mma.sync.aligned.m16n8k16.row.col.f32.f16.f16.f32 "
        "{%0,%1,%2,%3}, {%4,%5,%6,%7}, {%8,%9}, {%0,%1,%2,%3};"
        : "+f"(c[0]), "+f"(c[1]), "+f"(c[2]), "+f"(c[3])
        : "r"(a[0]), "r"(a[1]), "r"(a[2]), "r"(a[3]), "r"(b[0]), "r"(b[1]));
}
// correction products: fp16 operands, fp16 accumulate (rate probe: 2x on consumer lineage)
__device__ __forceinline__ void mma_f16acc(uint32_t* c, const uint32_t* a, const uint32_t* b) {
    asm volatile(
        "mma.sync.aligned.m16n8k16.row.col.f16.f16.f16.f16 "
        "{%0,%1}, {%2,%3,%4,%5}, {%6,%7}, {%0,%1};"
        : "+r"(c[0]), "+r"(c[1])
        : "r"(a[0]), "r"(a[1]), "r"(a[2]), "r"(a[3]), "r"(b[0]), "r"(b[1]));
}
__device__ __forceinline__ void split2h(float x, __half& h0, __half& h1) {
    h0 = __float2half_rn(x);
    h1 = __float2half_rn(x - __half2float(h0));
}

// ---------------- prologue: pack & split X = [old_h | input] ----------------
__global__ void pack_split_x(const float* __restrict__ old_h, const float* __restrict__ input,
                             __half* __restrict__ A0, __half* __restrict__ A1) {
    // each thread: 8 floats -> 16B stores to A0 and A1
    long i = (long)blockIdx.x * blockDim.x + threadIdx.x;   // float8 units, 4096*512
    int m = (int)(i >> 9);
    int kq = (int)(i & 511);     // octet index within row (512 octets of 8)
    const float4* src = (kq < 256) ? &reinterpret_cast<const float4*>(old_h)[(long)m * 512 + 2 * kq]
                                   : &reinterpret_cast<const float4*>(input)[(long)m * 512 + 2 * (kq - 256)];
    float4 v0 = src[0], v1 = src[1];
    __half h0[8], h1[8];
    split2h(v0.x, h0[0], h1[0]); split2h(v0.y, h0[1], h1[1]);
    split2h(v0.z, h0[2], h1[2]); split2h(v0.w, h0[3], h1[3]);
    split2h(v1.x, h0[4], h1[4]); split2h(v1.y, h0[5], h1[5]);
    split2h(v1.z, h0[6], h1[6]); split2h(v1.w, h0[7], h1[7]);
    *reinterpret_cast<uint4*>(&A0[8 * i]) = *reinterpret_cast<uint4*>(h0);
    *reinterpret_cast<uint4*>(&A1[8 * i]) = *reinterpret_cast<uint4*>(h1);
}

// ---------------- prologue: transpose & split W -> Wt[n][k], 16B stores ----------------
__global__ void split_w_kernel(const float* __restrict__ W,
                               __half* __restrict__ B0, __half* __restrict__ B1) {
    __shared__ float tile[32][33];
    int n0 = blockIdx.x * 32, k0 = blockIdx.y * 32;
    int tid = threadIdx.x;   // 128 threads
    // load 32k x 32n (coalesced over n)
#pragma unroll
    for (int e = 0; e < 8; e++) {
        int idx = tid + e * 128;
        int kr = idx >> 5, nc = idx & 31;
        tile[kr][nc] = W[(long)(k0 + kr) * NGATE + n0 + nc];
    }
    __syncthreads();
    // store: each thread handles one (n, k-octet): 32n x 4 octets = 128 tasks
    int n = tid >> 2, ko = (tid & 3) * 8;
    __half h0[8], h1[8];
#pragma unroll
    for (int j = 0; j < 8; j++)
        split2h(tile[ko + j][n], h0[j], h1[j]);
    long off = (long)(n0 + n) * KDIM + k0 + ko;
    *reinterpret_cast<uint4*>(&B0[off]) = *reinterpret_cast<uint4*>(h0);
    *reinterpret_cast<uint4*>(&B1[off]) = *reinterpret_cast<uint4*>(h1);
}

// ---------------- fused GEMM + LLTM epilogue ----------------
// CTA: 128 rows x 32 state-cols x 3 gates. 4 warps 4(m)x1(n), warp tile 32x96.
__global__ void __launch_bounds__(NTHREADS, 2) lltm_fused_kernel(
    const float* __restrict__ bias, const float* __restrict__ old_c,
    float* __restrict__ out) {
    extern __shared__ char smem[];
    const uint32_t sbase = smem_u32(smem);

    const int tid = threadIdx.x;
    const int warp = tid >> 5, lane = tid & 31;
    const int g = lane >> 2, t4 = lane & 3;
    const long m0 = (long)blockIdx.x * BM;
    const int n0s = blockIdx.y * BNS;        // state-column base (0..2047)

    float acc[2][12][4];
    uint32_t acch[2][12][2];
#pragma unroll
    for (int i = 0; i < 2; i++)
#pragma unroll
        for (int j = 0; j < 12; j++) {
#pragma unroll
            for (int r = 0; r < 4; r++) acc[i][j][r] = 0.0f;
            acch[i][j][0] = 0u;
            acch[i][j][1] = 0u;
        }

    // per-lane ldmatrix offsets (within a tile)
    const uint32_t a_off = (uint32_t)(warp * 32 + (lane & 15)) * ROWB + ((lane >> 4) << 4);
    const uint32_t b_off =
        (uint32_t)((lane & 7) + ((lane >> 4) << 3)) * ROWB + (((lane >> 3) & 1) << 4);

    auto issue_stage = [&](int t) {
        int slot = t % STAGES;
        long kk = (long)t * BK;
        uint32_t sA0 = sbase + slot * STAGE_BYTES;
        uint32_t sA1 = sA0 + A_T;
        uint32_t sB0 = sA1 + A_T;
        uint32_t sB1 = sB0 + B_T;
#pragma unroll
        for (int i = 0; i < 4; i++) {
            int q = tid + i * NTHREADS;
            int row = q >> 2, cw = q & 3;
            long goff = (m0 + row) * KDIM + kk + cw * 8;
            cp16(sA0 + row * ROWB + cw * 16, g_A0 + goff);
            cp16(sA1 + row * ROWB + cw * 16, g_A1 + goff);
        }
#pragma unroll
        for (int i = 0; i < 3; i++) {
            int q = tid + i * NTHREADS;
            int row = q >> 2, cw = q & 3;        // row 0..95
            long grow = (long)(row >> 5) * SDIM + n0s + (row & 31);
            long goff = grow * KDIM + kk + cw * 8;
            cp16(sB0 + row * ROWB + cw * 16, g_B0 + goff);
            cp16(sB1 + row * ROWB + cw * 16, g_B1 + goff);
        }
    };

#pragma unroll
    for (int s = 0; s < STAGES - 1; s++) {
        issue_stage(s);
        cp_commit();
    }

    for (int t = 0; t < KT; t++) {
        cp_wait<STAGES - 2>();
        __syncthreads();

        if (t + STAGES - 1 < KT) issue_stage(t + STAGES - 1);
        cp_commit();

        uint32_t sA0 = sbase + (t % STAGES) * STAGE_BYTES;
        uint32_t sA1 = sA0 + A_T;
        uint32_t sB0 = sA1 + A_T;
        uint32_t sB1 = sB0 + B_T;

#pragma unroll
        for (int s = 0; s < 2; s++) {            // 2 k16 slices per chunk
            const uint32_t ks = (uint32_t)s * 32;
            uint32_t a0[2][4], a1[2][4], b[12][2];
#pragma unroll
            for (int i = 0; i < 2; i++) {
                ldsm4(a0[i][0], a0[i][1], a0[i][2], a0[i][3],
                      sA0 + a_off + (uint32_t)i * (16 * ROWB) + ks);
                ldsm4(a1[i][0], a1[i][1], a1[i][2], a1[i][3],
                      sA1 + a_off + (uint32_t)i * (16 * ROWB) + ks);
            }
            // B0: main (fp32 acc) + correction A1*B0 (fp16 acc)
#pragma unroll
            for (int jj = 0; jj < 6; jj++)
                ldsm4(b[2 * jj][0], b[2 * jj][1], b[2 * jj + 1][0], b[2 * jj + 1][1],
                      sB0 + b_off + (uint32_t)jj * (16 * ROWB) + ks);
#pragma unroll
            for (int i = 0; i < 2; i++)
#pragma unroll
                for (int j = 0; j < 12; j++) mma_f32acc(acc[i][j], a0[i], b[j]);
#pragma unroll
            for (int i = 0; i < 2; i++)
#pragma unroll
                for (int j = 0; j < 12; j++) mma_f16acc(acch[i][j], a1[i], b[j]);
            // B1: correction A0*B1 (fp16 acc), reuse b regs
#pragma unroll
            for (int jj = 0; jj < 6; jj++)
                ldsm4(b[2 * jj][0], b[2 * jj][1], b[2 * jj + 1][0], b[2 * jj + 1][1],
                      sB1 + b_off + (uint32_t)jj * (16 * ROWB) + ks);
#pragma unroll
            for (int i = 0; i < 2; i++)
#pragma unroll
                for (int j = 0; j < 12; j++) mma_f16acc(acch[i][j], a0[i], b[j]);
        }
    }

    // ---- fused LLTM epilogue: gate = acc32 + f16tof32(acc16) ----
#pragma unroll
    for (int i = 0; i < 2; i++) {
        long row0 = m0 + warp * 32 + i * 16 + g;
#pragma unroll
        for (int sj = 0; sj < 4; sj++) {
            int col = n0s + sj * 8 + 2 * t4;
            float2 bi = *reinterpret_cast<const float2*>(&bias[col]);
            float2 bo = *reinterpret_cast<const float2*>(&bias[SDIM + col]);
            float2 bc = *reinterpret_cast<const float2*>(&bias[2 * SDIM + col]);
            const float* ai = acc[i][sj];
            const float* ao = acc[i][sj + 4];
            const float* ac = acc[i][sj + 8];
            const uint32_t* hi_ = acch[i][sj];
            const uint32_t* ho_ = acch[i][sj + 4];
            const uint32_t* hc_ = acch[i][sj + 8];
#pragma unroll
            for (int h = 0; h < 2; h++) {        // h=0: row0, h=1: row0+8
                long row = row0 + 8 * h;
                float2 ci = __half22float2(*reinterpret_cast<const __half2*>(&hi_[h]));
                float2 co = __half22float2(*reinterpret_cast<const __half2*>(&ho_[h]));
                float2 cc2 = __half22float2(*reinterpret_cast<const __half2*>(&hc_[h]));
                float2 oc = *reinterpret_cast<const float2*>(&old_c[row * SDIM + col]);
                float2 nh, ncell;
#define LANE(f, idx)                                                    \
                {                                                       \
                    float vi = ai[2 * h + idx] + ci.f + bi.f;           \
                    float vo = ao[2 * h + idx] + co.f + bo.f;           \
                    float vc = ac[2 * h + idx] + cc2.f + bc.f;          \
                    float ig = 1.0f / (1.0f + expf(-vi));               \
                    float og = 1.0f / (1.0f + expf(-vo));               \
                    float cel = (vc > 0.0f) ? vc : expm1f(vc);          \
                    float cell = oc.f + cel * ig;                       \
                    ncell.f = cell;                                     \
                    nh.f = tanhf(cell) * og;                            \
                }
                LANE(x, 0) LANE(y, 1)
#undef LANE
                *reinterpret_cast<float2*>(&out[row * SDIM + col]) = nh;
                *reinterpret_cast<float2*>(&out[HSIZE + row * SDIM + col]) = ncell;
            }
        }
    }
}

// ---------------- host ----------------
extern "C" void kernel_launch(void* const* d_in, const int* in_sizes, int n_in,
                              void* d_out, int out_size) {
    const float* W     = (const float*)d_in[0];   // (4096, 6144)
    const float* bias  = (const float*)d_in[1];   // (6144,)
    const float* input = (const float*)d_in[2];   // (4096, 2048)
    const float* old_h = (const float*)d_in[3];   // (4096, 2048)
    const float* old_c = (const float*)d_in[4];   // (4096, 2048)
    float* out = (float*)d_out;                   // [new_h | new_cell]

    void *pA0, *pA1, *pB0, *pB1;
    cudaGetSymbolAddress(&pA0, g_A0);
    cudaGetSymbolAddress(&pA1, g_A1);
    cudaGetSymbolAddress(&pB0, g_B0);
    cudaGetSymbolAddress(&pB1, g_B1);

    pack_split_x<<<8192, 256>>>(old_h, input, (__half*)pA0, (__half*)pA1);
    split_w_kernel<<<dim3(NGATE / 32, KDIM / 32), 128>>>(W, (__half*)pB0, (__half*)pB1);

    cudaFuncSetAttribute(lltm_fused_kernel, cudaFuncAttributeMaxDynamicSharedMemorySize,
                         SMEM_TOTAL);
    lltm_fused_kernel<<<dim3(BDIM / BM, SDIM / BNS), NTHREADS, SMEM_TOTAL>>>(bias, old_c, out);
}